// round 13
// baseline (speedup 1.0000x reference)
#include <cuda_runtime.h>
#include <stdint.h>

// Problem constants (fixed by the reference).
static constexpr int P  = 16;    // permutations
static constexpr int B  = 4096;  // batch
static constexpr int NB = 256;   // blocks per permutation (D/STEP)
static constexpr int D  = 1024;  // feature dim
static constexpr int ROWS = 8;   // batch rows per thread in main kernel

// Scratch: perm table extracted from T each call (no caching allowed).
__device__ int g_perm[P * NB];

// ---------------------------------------------------------------------------
// Kernel 1: extract the block permutation from the dense T matrices.
// T[i, 4r:4r+4, 4c:4c+4] = I  when perm_i[r] = c.
// One warp per (i, r): lanes scan c, exactly one lane finds the 1.0.
// ---------------------------------------------------------------------------
__global__ void extract_perms_kernel(const float* __restrict__ T) {
    int warp_global = (blockIdx.x * blockDim.x + threadIdx.x) >> 5;
    int lane = threadIdx.x & 31;
    if (warp_global >= P * NB) return;
    int i = warp_global >> 8;      // permutation index
    int r = warp_global & (NB - 1);
    const float* row = T + ((size_t)i * D + 4 * r) * D;  // row o = 4r of T[i]
#pragma unroll
    for (int k = 0; k < NB / 32; ++k) {
        int c = lane + 32 * k;
        // exactly one c has a 1.0 on this row at column 4c
        if (row[4 * c] > 0.5f) g_perm[warp_global] = c;
    }
}

// ---------------------------------------------------------------------------
// Kernel 2: apply the gather.
//   out[(g*B + b), :]  with column blocks permuted by perm[indices[g]].
// float4 granularity (STEP=4, 16B aligned).
// Grid order: group index INNER so the 16 blocks reading the same x rows are
// co-resident -> x stays L2-hot. Streaming stores (__stcs) keep the 256MB
// write stream from evicting x.
// One block = 256 threads (one per output float4 column) x ROWS batch rows.
// ---------------------------------------------------------------------------
__global__ void __launch_bounds__(256)
permute_gather_kernel(const float4* __restrict__ x4,
                      const int*    __restrict__ indices,
                      float4*       __restrict__ out4) {
    const int tid = threadIdx.x;                 // output column block 0..255
    const int grp     = blockIdx.x % P;          // inner: group (x-row reuse)
    const int b_chunk = blockIdx.x / P;          // outer: batch chunk
    const int b0 = b_chunk * ROWS;

    const int j    = __ldg(&indices[grp]);       // which permutation
    const int pblk = g_perm[j * NB + tid];       // source column block

    const float4* src = x4 + pblk;                                   // + b*NB
    float4* dst = out4 + ((size_t)grp * B + b0) * NB + tid;          // + k*NB

    float4 v[ROWS];
#pragma unroll
    for (int k = 0; k < ROWS; ++k)
        v[k] = __ldg(src + (size_t)(b0 + k) * NB);
#pragma unroll
    for (int k = 0; k < ROWS; ++k)
        __stcs(dst + (size_t)k * NB, v[k]);      // evict-first streaming store
}

// ---------------------------------------------------------------------------
// Launch
// ---------------------------------------------------------------------------
extern "C" void kernel_launch(void* const* d_in, const int* in_sizes, int n_in,
                              void* d_out, int out_size) {
    const float* x   = (const float*)d_in[0];   // [B, D] fp32
    const float* T   = (const float*)d_in[1];   // [P, D, D] fp32
    const int*   idx = (const int*)d_in[2];     // [P] int32
    float* out = (float*)d_out;                 // [P*B, D] fp32

    // 1) Extract permutations: P*NB = 4096 warps -> 512 blocks x 256 threads.
    extract_perms_kernel<<<(P * NB * 32 + 255) / 256, 256>>>(T);

    // 2) Gather: (B/ROWS) batch chunks x P groups, group-inner ordering.
    permute_gather_kernel<<<(B / ROWS) * P, 256>>>(
        (const float4*)x, idx, (float4*)out);
}

// round 14
// speedup vs baseline: 1.1643x; 1.1643x over previous
#include <cuda_runtime.h>
#include <stdint.h>

// Problem constants (fixed by the reference).
static constexpr int P  = 16;    // permutations
static constexpr int B  = 4096;  // batch
static constexpr int NB = 256;   // float4 blocks per row (D/STEP)
static constexpr int D  = 1024;  // feature dim
static constexpr int ROWS = 8;   // batch rows staged per block

// Scratch: perm table extracted from T each call (no caching allowed).
__device__ int g_perm[P * NB];

// ---------------------------------------------------------------------------
// Kernel 1: extract the block permutation from the dense T matrices.
// T[i, 4r:4r+4, 4c:4c+4] = I  when perm_i[r] = c.
// One warp per (i, r): lanes scan c, exactly one lane finds the 1.0.
// ---------------------------------------------------------------------------
__global__ void extract_perms_kernel(const float* __restrict__ T) {
    int warp_global = (blockIdx.x * blockDim.x + threadIdx.x) >> 5;
    int lane = threadIdx.x & 31;
    if (warp_global >= P * NB) return;
    int i = warp_global >> 8;      // permutation index
    int r = warp_global & (NB - 1);
    const float* row = T + ((size_t)i * D + 4 * r) * D;  // row o = 4r of T[i]
#pragma unroll
    for (int k = 0; k < NB / 32; ++k) {
        int c = lane + 32 * k;
        if (row[4 * c] > 0.5f) g_perm[warp_global] = c;
    }
}

// ---------------------------------------------------------------------------
// Kernel 2: smem-staged shuffle.
// Block = one batch chunk of ROWS rows, serving ALL 16 groups:
//   1) coalesced LDG.128 of 8 x-rows into smem (32 KB)
//   2) for each (grp, row): LDS at permuted column, coalesced __stcs STG.128
// Both global streams are fully coalesced; the random permutation is absorbed
// by the smem crossbar (random bank conflicts ~2-3x, bandwidth to spare).
// Each x-row is read from global exactly once for all 16 output groups.
// ---------------------------------------------------------------------------
__global__ void __launch_bounds__(256)
permute_shuffle_kernel(const float4* __restrict__ x4,
                       const int*    __restrict__ indices,
                       float4*       __restrict__ out4) {
    __shared__ float4 s[ROWS * NB];              // 32 KB

    const int tid = threadIdx.x;                 // column block 0..255
    const int b0  = blockIdx.x * ROWS;

    // Stage 8 rows of x, coalesced.
#pragma unroll
    for (int k = 0; k < ROWS; ++k)
        s[k * NB + tid] = __ldg(x4 + (size_t)(b0 + k) * NB + tid);

    // Precompute this thread's source block for every group (registers).
    int pblk[P];
#pragma unroll
    for (int g = 0; g < P; ++g) {
        int j = __ldg(&indices[g]);
        pblk[g] = g_perm[j * NB + tid];
    }

    __syncthreads();

    // Emit 16 permuted copies, coalesced streaming stores.
#pragma unroll 2
    for (int g = 0; g < P; ++g) {
        float4* dst = out4 + ((size_t)g * B + b0) * NB + tid;
        const int pb = pblk[g];
#pragma unroll
        for (int k = 0; k < ROWS; ++k) {
            float4 v = s[k * NB + pb];
            __stcs(dst + (size_t)k * NB, v);     // evict-first: 256MB write
        }                                        // stream must not evict x/T
    }
}

// ---------------------------------------------------------------------------
// Launch
// ---------------------------------------------------------------------------
extern "C" void kernel_launch(void* const* d_in, const int* in_sizes, int n_in,
                              void* d_out, int out_size) {
    const float* x   = (const float*)d_in[0];   // [B, D] fp32
    const float* T   = (const float*)d_in[1];   // [P, D, D] fp32
    const int*   idx = (const int*)d_in[2];     // [P] int32
    float* out = (float*)d_out;                 // [P*B, D] fp32

    // 1) Extract permutations: P*NB = 4096 warps -> 512 blocks x 256 threads.
    extract_perms_kernel<<<(P * NB * 32 + 255) / 256, 256>>>(T);

    // 2) Shuffle: one block per 8-row batch chunk (512 blocks), all groups.
    permute_shuffle_kernel<<<B / ROWS, 256>>>(
        (const float4*)x, idx, (float4*)out);
}

// round 15
// speedup vs baseline: 1.2240x; 1.0513x over previous
#include <cuda_runtime.h>
#include <stdint.h>

// Problem constants (fixed by the reference).
static constexpr int P  = 16;    // permutations
static constexpr int B  = 4096;  // batch
static constexpr int NB = 256;   // float4 blocks per row (D/STEP)
static constexpr int D  = 1024;  // feature dim
static constexpr int ROWS = 4;   // batch rows staged per block (was 8)

// Scratch: perm table extracted from T each call (no caching allowed).
__device__ int g_perm[P * NB];

// ---------------------------------------------------------------------------
// Kernel 1: extract the block permutation from the dense T matrices.
// T[i, 4r:4r+4, 4c:4c+4] = I  when perm_i[r] = c.
// One warp per (i, r): lanes scan c, exactly one lane finds the 1.0.
// ---------------------------------------------------------------------------
__global__ void extract_perms_kernel(const float* __restrict__ T) {
    int warp_global = (blockIdx.x * blockDim.x + threadIdx.x) >> 5;
    int lane = threadIdx.x & 31;
    if (warp_global >= P * NB) return;
    int i = warp_global >> 8;      // permutation index
    int r = warp_global & (NB - 1);
    const float* row = T + ((size_t)i * D + 4 * r) * D;  // row o = 4r of T[i]
#pragma unroll
    for (int k = 0; k < NB / 32; ++k) {
        int c = lane + 32 * k;
        if (row[4 * c] > 0.5f) g_perm[warp_global] = c;
    }
}

// ---------------------------------------------------------------------------
// Kernel 2: smem-staged shuffle, occupancy-tuned.
// Block = 4 batch rows (16 KB smem), serving ALL 16 groups:
//   1) coalesced LDG.128 of 4 x-rows into smem
//   2) per group: pblk from L1-resident g_perm, 4x LDS batched, then
//      4x coalesced __stcs STG.128
// grid = 1024 CTAs -> ~7 CTAs/SM; low regs (no pblk[] array) -> high occ.
// ---------------------------------------------------------------------------
__global__ void __launch_bounds__(256, 6)
permute_shuffle_kernel(const float4* __restrict__ x4,
                       const int*    __restrict__ indices,
                       float4*       __restrict__ out4) {
    __shared__ float4 s[ROWS * NB];              // 16 KB
    __shared__ int    idx_s[P];

    const int tid = threadIdx.x;                 // column block 0..255
    const int b0  = blockIdx.x * ROWS;

    if (tid < P) idx_s[tid] = __ldg(&indices[tid]);

    // Stage 4 rows of x, coalesced.
#pragma unroll
    for (int k = 0; k < ROWS; ++k)
        s[k * NB + tid] = __ldg(x4 + (size_t)(b0 + k) * NB + tid);

    __syncthreads();

    // Emit 16 permuted copies, coalesced streaming stores.
#pragma unroll 4
    for (int g = 0; g < P; ++g) {
        const int j  = idx_s[g];
        const int pb = __ldg(&g_perm[j * NB + tid]);   // 16KB table, L1-hot
        float4* dst = out4 + ((size_t)g * B + b0) * NB + tid;

        float4 v[ROWS];
#pragma unroll
        for (int k = 0; k < ROWS; ++k)
            v[k] = s[k * NB + pb];                     // batched LDS (MLP)
#pragma unroll
        for (int k = 0; k < ROWS; ++k)
            __stcs(dst + (size_t)k * NB, v[k]);        // evict-first stores
    }
}

// ---------------------------------------------------------------------------
// Launch
// ---------------------------------------------------------------------------
extern "C" void kernel_launch(void* const* d_in, const int* in_sizes, int n_in,
                              void* d_out, int out_size) {
    const float* x   = (const float*)d_in[0];   // [B, D] fp32
    const float* T   = (const float*)d_in[1];   // [P, D, D] fp32
    const int*   idx = (const int*)d_in[2];     // [P] int32
    float* out = (float*)d_out;                 // [P*B, D] fp32

    // 1) Extract permutations: P*NB = 4096 warps -> 512 blocks x 256 threads.
    extract_perms_kernel<<<(P * NB * 32 + 255) / 256, 256>>>(T);

    // 2) Shuffle: one block per 4-row batch chunk (1024 blocks), all groups.
    permute_shuffle_kernel<<<B / ROWS, 256>>>(
        (const float4*)x, idx, (float4*)out);
}